// round 6
// baseline (speedup 1.0000x reference)
#include <cuda_runtime.h>
#include <cstdint>
#include <math.h>

// Problem constants
#define T_SEQ 2048
#define H     256
#define G3    768          // 3*H gate rows
#define VOUT  32000

// Scan cluster config
#define CLN          8     // cluster size
#define SLICE        32    // hidden units per CTA (H / CLN)
#define ROWS_PER_CTA 96    // 3 * SLICE rows of W_hh per CTA
#define WPITCH       272   // padded row pitch (floats) -> conflict-free LDS.128
#define SCAN_THREADS 384   // 96 row-teams * 4 lanes

// ---------------------------------------------------------------------------
// Device scratch (static __device__ arrays: allocation-free per harness rules)
// ---------------------------------------------------------------------------
__device__ __align__(16) float g_Xenc[T_SEQ * H];
__device__ __align__(16) float g_Xdec[T_SEQ * H];
__device__ __align__(16) float g_gi_enc[T_SEQ * G3];
__device__ __align__(16) float g_gi_dec[T_SEQ * G3];
__device__ __align__(16) float g_Hs[T_SEQ * H];
__device__ __align__(16) float g_sumexp[T_SEQ];

// ---------------------------------------------------------------------------
// 1) Gather embeddings (+ relu for decoder input) and zero the sum-exp accum.
// ---------------------------------------------------------------------------
__global__ void gather_kernel(const int* __restrict__ src, const int* __restrict__ trg,
                              const float* __restrict__ enc_emb,
                              const float* __restrict__ dec_emb)
{
    int t = blockIdx.x;
    int i = threadIdx.x;           // 256 threads
    int s = src[t];
    int d = trg[t];
    g_Xenc[t * H + i] = enc_emb[(size_t)s * H + i];
    float v = dec_emb[(size_t)d * H + i];
    g_Xdec[t * H + i] = v > 0.f ? v : 0.f;
    if (t < T_SEQ / H) g_sumexp[t * H + i] = 0.f;   // 8 blocks zero all 2048 entries
}

// ---------------------------------------------------------------------------
// 2) Generic fp32 GEMM: C[M][N] = A[M][256] * B[N][256]^T + bias[N]
//    Tiles 64x64, K fixed = 256 (BK=16). 256 threads, 4x4 micro-tile.
//    do_lse: accumulate per-row sum(exp(c)) into g_sumexp (logits GEMM only).
//    Requires M % 64 == 0 and N % 64 == 0 (2048 / 768 / 32000 all qualify).
// ---------------------------------------------------------------------------
__global__ __launch_bounds__(256)
void gemm_kernel(const float* __restrict__ A, const float* __restrict__ B,
                 const float* __restrict__ bias, float* __restrict__ C,
                 int N, int do_lse)
{
    __shared__ float As[16][68];   // [k][m], padded
    __shared__ float Bs[16][68];   // [k][n], padded

    int tid = threadIdx.x;
    int tx = tid & 15;
    int ty = tid >> 4;
    int bm = blockIdx.x * 64;
    int bn = blockIdx.y * 64;

    int lr = tid >> 2;             // 0..63 : tile row for loads
    int lk = (tid & 3) * 4;        // 0,4,8,12 : k offset for loads

    const float* Ap = A + (size_t)(bm + lr) * 256 + lk;
    const float* Bp = B + (size_t)(bn + lr) * 256 + lk;

    float acc[4][4] = {};

    for (int kb = 0; kb < 256; kb += 16) {
        float4 a = *(const float4*)(Ap + kb);
        float4 b = *(const float4*)(Bp + kb);
        __syncthreads();
        As[lk + 0][lr] = a.x; As[lk + 1][lr] = a.y; As[lk + 2][lr] = a.z; As[lk + 3][lr] = a.w;
        Bs[lk + 0][lr] = b.x; Bs[lk + 1][lr] = b.y; Bs[lk + 2][lr] = b.z; Bs[lk + 3][lr] = b.w;
        __syncthreads();
#pragma unroll
        for (int kk = 0; kk < 16; kk++) {
            float4 av = *(const float4*)&As[kk][ty * 4];
            float4 bv = *(const float4*)&Bs[kk][tx * 4];
            acc[0][0] += av.x * bv.x; acc[0][1] += av.x * bv.y; acc[0][2] += av.x * bv.z; acc[0][3] += av.x * bv.w;
            acc[1][0] += av.y * bv.x; acc[1][1] += av.y * bv.y; acc[1][2] += av.y * bv.z; acc[1][3] += av.y * bv.w;
            acc[2][0] += av.z * bv.x; acc[2][1] += av.z * bv.y; acc[2][2] += av.z * bv.z; acc[2][3] += av.z * bv.w;
            acc[3][0] += av.w * bv.x; acc[3][1] += av.w * bv.y; acc[3][2] += av.w * bv.z; acc[3][3] += av.w * bv.w;
        }
    }

    float4 bb = *(const float4*)(bias + bn + tx * 4);
#pragma unroll
    for (int i = 0; i < 4; i++) {
        int row = bm + ty * 4 + i;
        float4 o;
        o.x = acc[i][0] + bb.x;
        o.y = acc[i][1] + bb.y;
        o.z = acc[i][2] + bb.z;
        o.w = acc[i][3] + bb.w;
        *(float4*)(C + (size_t)row * N + bn + tx * 4) = o;
        if (do_lse) {
            // logits bounded by ~16.1 -> max-free sum-exp is safe in fp32
            float s = expf(o.x) + expf(o.y) + expf(o.z) + expf(o.w);
            s += __shfl_xor_sync(0xffffffffu, s, 1);
            s += __shfl_xor_sync(0xffffffffu, s, 2);
            s += __shfl_xor_sync(0xffffffffu, s, 4);
            s += __shfl_xor_sync(0xffffffffu, s, 8);
            if (tx == 0) atomicAdd(&g_sumexp[row], s);
        }
    }
}

// ---------------------------------------------------------------------------
// 3) Sequential GRU scan, single 8-CTA cluster.
//    CTA c owns hidden units [32c, 32c+32) and the matching 96 rows of each
//    W_hh (rows g*256 + 32c + j). Weights live in SMEM (padded pitch 272 for
//    conflict-free LDS.128). h is replicated per CTA, double-buffered; each
//    CTA pushes its 32 new h values to all peers via mapa + st.shared::cluster,
//    sealed by one barrier.cluster per half-step.
// ---------------------------------------------------------------------------
#define CLUSTER_SYNC_() do { \
    asm volatile("barrier.cluster.arrive.aligned;" ::: "memory"); \
    asm volatile("barrier.cluster.wait.aligned;"   ::: "memory"); \
} while (0)

__device__ __forceinline__ void half_step(
    const float* __restrict__ W, float* hb, float* ghbuf,
    int p, int tid, int unit,
    float g_r, float g_z, float g_n,
    float b_r, float b_z, float b_n,
    bool write_hs, int t)
{
    int rt = tid >> 2;             // row team 0..95  (g*32 + j)
    int m  = tid & 3;              // lane within team
    const float* Wrow = W + rt * WPITCH;
    const float* hp   = hb + p * H;

    float a0 = 0.f, a1 = 0.f, a2 = 0.f, a3 = 0.f;
#pragma unroll
    for (int it = 0; it < 16; it++) {
        int ch = (it * 4 + m) * 4;                     // float offset, 16B chunks
        float4 w  = *(const float4*)(Wrow + ch);
        float4 hv = *(const float4*)(hp + ch);
        a0 += w.x * hv.x; a1 += w.y * hv.y; a2 += w.z * hv.z; a3 += w.w * hv.w;
    }
    float acc = (a0 + a1) + (a2 + a3);
    acc += __shfl_xor_sync(0xffffffffu, acc, 1);
    acc += __shfl_xor_sync(0xffffffffu, acc, 2);
    if (m == 0) ghbuf[rt] = acc;
    __syncthreads();

    if (tid < SLICE) {
        float r = 1.f / (1.f + expf(-(g_r + ghbuf[tid]      + b_r)));
        float z = 1.f / (1.f + expf(-(g_z + ghbuf[32 + tid] + b_z)));
        float n = tanhf(g_n + r * (ghbuf[64 + tid] + b_n));
        float hold = hp[unit];
        float hnew = (1.f - z) * n + z * hold;
        if (write_hs) g_Hs[t * H + unit] = hnew;
        // broadcast new h[unit] to every CTA's (p^1) buffer (incl. self)
        uint32_t laddr = (uint32_t)__cvta_generic_to_shared(hb + ((p ^ 1) * H) + unit);
#pragma unroll
        for (int dst = 0; dst < CLN; dst++) {
            uint32_t raddr;
            asm("mapa.shared::cluster.u32 %0, %1, %2;" : "=r"(raddr) : "r"(laddr), "r"(dst));
            asm volatile("st.shared::cluster.f32 [%0], %1;" :: "r"(raddr), "f"(hnew));
        }
    }
    CLUSTER_SYNC_();  // release/acquire: peers' h(p^1) updates visible to all
}

__global__ void __cluster_dims__(CLN, 1, 1) __launch_bounds__(SCAN_THREADS, 1)
scan_kernel(const float* __restrict__ eWhh, const float* __restrict__ eBhh,
            const float* __restrict__ dWhh, const float* __restrict__ dBhh)
{
    extern __shared__ float sm[];
    float* We    = sm;                                  // 96 * 272
    float* Wd    = We + ROWS_PER_CTA * WPITCH;          // 96 * 272
    float* hb    = Wd + ROWS_PER_CTA * WPITCH;          // 2 * 256 (double buffer)
    float* ghbuf = hb + 2 * H;                          // 96

    int tid = threadIdx.x;
    int c = blockIdx.x;                                 // slice owner id (grid == 1 cluster)

    // Load this CTA's 96 rows of each W_hh into padded SMEM
    for (int idx = tid; idx < ROWS_PER_CTA * 64; idx += SCAN_THREADS) {
        int lr = idx >> 6;
        int q  = (idx & 63) * 4;
        int g  = lr >> 5;
        int j  = lr & 31;
        size_t off = (size_t)(g * H + c * SLICE + j) * H + q;
        *(float4*)(We + lr * WPITCH + q) = *(const float4*)(eWhh + off);
        *(float4*)(Wd + lr * WPITCH + q) = *(const float4*)(dWhh + off);
    }
    for (int i = tid; i < 2 * H; i += SCAN_THREADS) hb[i] = 0.f;

    int unit = c * SLICE + tid;                         // valid when tid < 32
    float be_r = 0.f, be_z = 0.f, be_n = 0.f, bd_r = 0.f, bd_z = 0.f, bd_n = 0.f;
    if (tid < SLICE) {
        be_r = eBhh[unit]; be_z = eBhh[H + unit]; be_n = eBhh[2 * H + unit];
        bd_r = dBhh[unit]; bd_z = dBhh[H + unit]; bd_n = dBhh[2 * H + unit];
    }
    CLUSTER_SYNC_();   // all buffers initialized before any peer DSMEM write

    for (int t = 0; t < T_SEQ; t++) {
        // prefetch precomputed gi for this step (hidden under matvec latency)
        float ge_r = 0.f, ge_z = 0.f, ge_n = 0.f, gd_r = 0.f, gd_z = 0.f, gd_n = 0.f;
        if (tid < SLICE) {
            const float* gie = g_gi_enc + t * G3 + unit;
            ge_r = gie[0]; ge_z = gie[H]; ge_n = gie[2 * H];
            const float* gid = g_gi_dec + t * G3 + unit;
            gd_r = gid[0]; gd_z = gid[H]; gd_n = gid[2 * H];
        }
        // encoder: read h(0) -> write h(1)
        half_step(We, hb, ghbuf, 0, tid, unit, ge_r, ge_z, ge_n, be_r, be_z, be_n, false, t);
        // decoder: read h(1) -> write h(0); also record h into g_Hs
        half_step(Wd, hb, ghbuf, 1, tid, unit, gd_r, gd_z, gd_n, bd_r, bd_z, bd_n, true, t);
    }
}

// ---------------------------------------------------------------------------
// 4) log-softmax fix-up: out[t][v] = logit - log(sumexp[t])
// ---------------------------------------------------------------------------
__global__ void finalize_kernel(float* __restrict__ out)
{
    int i = blockIdx.x * blockDim.x + threadIdx.x;
    int total4 = T_SEQ * (VOUT / 4);
    int stride = gridDim.x * blockDim.x;
    float4* o4 = (float4*)out;
    for (; i < total4; i += stride) {
        int row = i / (VOUT / 4);
        float l = logf(g_sumexp[row]);
        float4 v = o4[i];
        v.x -= l; v.y -= l; v.z -= l; v.w -= l;
        o4[i] = v;
    }
}

// ---------------------------------------------------------------------------
// Launch (graph-capturable: kernel launches only on the default stream)
// ---------------------------------------------------------------------------
extern "C" void kernel_launch(void* const* d_in, const int* in_sizes, int n_in,
                              void* d_out, int out_size)
{
    const int*   src      = (const int*)  d_in[0];
    const int*   trg      = (const int*)  d_in[1];
    const float* enc_emb  = (const float*)d_in[2];
    const float* enc_W_ih = (const float*)d_in[3];
    const float* enc_W_hh = (const float*)d_in[4];
    const float* enc_b_ih = (const float*)d_in[5];
    const float* enc_b_hh = (const float*)d_in[6];
    const float* dec_emb  = (const float*)d_in[7];
    const float* dec_W_ih = (const float*)d_in[8];
    const float* dec_W_hh = (const float*)d_in[9];
    const float* dec_b_ih = (const float*)d_in[10];
    const float* dec_b_hh = (const float*)d_in[11];
    const float* out_W    = (const float*)d_in[12];
    const float* out_b    = (const float*)d_in[13];
    float* out = (float*)d_out;

    float *pXe, *pXd, *pGe, *pGd, *pHs;
    cudaGetSymbolAddress((void**)&pXe, g_Xenc);
    cudaGetSymbolAddress((void**)&pXd, g_Xdec);
    cudaGetSymbolAddress((void**)&pGe, g_gi_enc);
    cudaGetSymbolAddress((void**)&pGd, g_gi_dec);
    cudaGetSymbolAddress((void**)&pHs, g_Hs);

    const int scan_smem = (2 * ROWS_PER_CTA * WPITCH + 2 * H + SLICE * 3) * (int)sizeof(float);
    cudaFuncSetAttribute(scan_kernel, cudaFuncAttributeMaxDynamicSharedMemorySize, scan_smem);

    // 1) gather x vectors (+ relu) and zero sum-exp accumulators
    gather_kernel<<<T_SEQ, 256>>>(src, trg, enc_emb, dec_emb);

    // 2) precompute input-side gate pre-activations (parallel over all t)
    gemm_kernel<<<dim3(T_SEQ / 64, G3 / 64), 256>>>(pXe, enc_W_ih, enc_b_ih, pGe, G3, 0);
    gemm_kernel<<<dim3(T_SEQ / 64, G3 / 64), 256>>>(pXd, dec_W_ih, dec_b_ih, pGd, G3, 0);

    // 3) sequential GRU scan (one 8-CTA cluster, weights SMEM-resident)
    scan_kernel<<<CLN, SCAN_THREADS, scan_smem>>>(enc_W_hh, enc_b_hh, dec_W_hh, dec_b_hh);

    // 4) output projection + per-row sum-exp epilogue
    gemm_kernel<<<dim3(T_SEQ / 64, VOUT / 64), 256>>>(pHs, out_W, out_b, out, VOUT, 1);

    // 5) log-softmax fix-up
    finalize_kernel<<<2048, 256>>>(out);
}